// round 1
// baseline (speedup 1.0000x reference)
#include <cuda_runtime.h>
#include <math.h>

#define BB   16
#define SS   1024
#define EE   300
#define HH   128
#define H2   256
#define NHD  4
#define G3   384
#define NOUT 3
#define SB   (SS*BB)   // 16384

// ---------------- scratch (static device globals; no allocations) ----------------
__device__ float g_gx[2][SB][G3];          // gate preactivations, both directions (~50 MB)
__device__ float g_rh[BB][SS][H2];         // concat GRU hidden states (~17 MB)
__device__ float g_q[BB][NHD][SS][H2];     // per-head query = rh @ W_m[h] (~67 MB)
__device__ float g_alpha[BB][NHD][SS][SS]; // attention scores / weights (~268 MB)
__device__ float g_att[BB][SS][H2];        // head-combined attention output (~17 MB)
__device__ int   g_is64;                   // review dtype detector

__device__ __forceinline__ float sigmoidf_(float x){ return 1.0f/(1.0f+__expf(-x)); }

// 4x4 microtile FMA macro
#define MM16(a,b4) \
  acc[0][0]=fmaf(a.x,b4.x,acc[0][0]); acc[0][1]=fmaf(a.x,b4.y,acc[0][1]); \
  acc[0][2]=fmaf(a.x,b4.z,acc[0][2]); acc[0][3]=fmaf(a.x,b4.w,acc[0][3]); \
  acc[1][0]=fmaf(a.y,b4.x,acc[1][0]); acc[1][1]=fmaf(a.y,b4.y,acc[1][1]); \
  acc[1][2]=fmaf(a.y,b4.z,acc[1][2]); acc[1][3]=fmaf(a.y,b4.w,acc[1][3]); \
  acc[2][0]=fmaf(a.z,b4.x,acc[2][0]); acc[2][1]=fmaf(a.z,b4.y,acc[2][1]); \
  acc[2][2]=fmaf(a.z,b4.z,acc[2][2]); acc[2][3]=fmaf(a.z,b4.w,acc[2][3]); \
  acc[3][0]=fmaf(a.w,b4.x,acc[3][0]); acc[3][1]=fmaf(a.w,b4.y,acc[3][1]); \
  acc[3][2]=fmaf(a.w,b4.z,acc[3][2]); acc[3][3]=fmaf(a.w,b4.w,acc[3][3]);

#define SCAT_A(v) As[4*lq+0][la]=v.x; As[4*lq+1][la]=v.y; As[4*lq+2][la]=v.z; As[4*lq+3][la]=v.w;
#define SCAT_B(v) Bs[4*lq+0][la]=v.x; Bs[4*lq+1][la]=v.y; Bs[4*lq+2][la]=v.z; Bs[4*lq+3][la]=v.w;

// ---------------- detector: is review int64 (odd 32-bit words all zero)? ----------------
__global__ void k_detect(const int* __restrict__ review){
    // check the high words of the first 256 putative int64 elements
    __shared__ int nz;
    if (threadIdx.x == 0) nz = 0;
    __syncthreads();
    for (int i = threadIdx.x; i < 256; i += 32)
        if (review[2*i+1] != 0) atomicAdd(&nz, 1);
    __syncthreads();
    if (threadIdx.x == 0) g_is64 = (nz == 0) ? 1 : 0;
}

// ---------------- K1: gx = gather(emb) @ w_ih^T + b_ih  (both directions) ----------------
__global__ __launch_bounds__(256) void k_gx(const int* __restrict__ review,
                                            const float* __restrict__ emb,
                                            const float* __restrict__ wf, const float* __restrict__ bf,
                                            const float* __restrict__ wb, const float* __restrict__ bbp)
{
    const int dir = blockIdx.z;
    const float* w    = dir ? wb  : wf;
    const float* bias = dir ? bbp : bf;
    __shared__ float As[16][68];
    __shared__ float Bs[16][68];
    __shared__ int   stok[64];
    const int tid = threadIdx.x;
    const int m0 = blockIdx.y*64, n0 = blockIdx.x*64;
    const int is64 = g_is64;
    if (tid < 64){
        int m = m0 + tid;
        int s = m >> 4, b = m & 15;
        int p = dir ? (SS-1-s) : s;
        int idx = b*SS + p;
        stok[tid] = is64 ? review[2*idx] : review[idx];
    }
    const int tr = tid>>4, tc = tid&15;
    const int la = tid>>2, lq = tid&3;
    float acc[4][4] = {};
    __syncthreads();
    const int tokla = stok[la];
    for (int k0 = 0; k0 < 304; k0 += 16){
        int kk = k0 + 4*lq;
        float4 av = make_float4(0.f,0.f,0.f,0.f);
        float4 bv = make_float4(0.f,0.f,0.f,0.f);
        if (kk < EE){
            av = *(const float4*)(emb + (size_t)tokla*EE + kk);
            bv = *(const float4*)(w   + (size_t)(n0+la)*EE + kk);
        }
        __syncthreads();
        SCAT_A(av); SCAT_B(bv);
        __syncthreads();
        #pragma unroll
        for (int kk2 = 0; kk2 < 16; kk2++){
            float4 a  = *(const float4*)&As[kk2][4*tr];
            float4 b4 = *(const float4*)&Bs[kk2][4*tc];
            MM16(a,b4);
        }
    }
    #pragma unroll
    for (int i = 0; i < 4; i++){
        int gm = m0 + 4*tr + i;
        float4 o;
        o.x = acc[i][0] + bias[n0+4*tc+0];
        o.y = acc[i][1] + bias[n0+4*tc+1];
        o.z = acc[i][2] + bias[n0+4*tc+2];
        o.w = acc[i][3] + bias[n0+4*tc+3];
        *(float4*)&g_gx[dir][gm][n0+4*tc] = o;
    }
}

// ---------------- K2: GRU recurrence (one block per (batch, direction)) ----------------
__global__ __launch_bounds__(128) void k_gru(const float* __restrict__ whhf, const float* __restrict__ bhhf,
                                             const float* __restrict__ whhb, const float* __restrict__ bhhb)
{
    extern __shared__ float smdyn[];
    float* sws  = smdyn;                  // [3*128][132] w_hh, row stride 132 (conflict-free float4)
    float* hbuf = smdyn + 3*128*132;      // [2][128] ping-pong hidden state
    const int b = blockIdx.x, dir = blockIdx.y;
    const float* whh = dir ? whhb : whhf;
    const float* bhh = dir ? bhhb : bhhf;
    const int t = threadIdx.x;

    for (int idx = t; idx < 3*128*128; idx += 128){
        int j = idx >> 7, k = idx & 127;
        sws[j*132 + k] = whh[idx];
    }
    hbuf[t] = 0.f; hbuf[128+t] = 0.f;
    float bhr = bhh[t], bhz = bhh[HH+t], bhn = bhh[2*HH+t];
    const float* wr = sws + (size_t)t*132;
    const float* wz = sws + (size_t)(HH+t)*132;
    const float* wn = sws + (size_t)(2*HH+t)*132;
    const float* gxbase = &g_gx[dir][0][0] + b*G3;
    float hself = 0.f;
    __syncthreads();

    for (int i = 0; i < SS; i++){
        const float* gx = gxbase + (size_t)i*(BB*G3);
        float xr = gx[t], xz = gx[HH+t], xn = gx[2*HH+t];   // prefetch early
        const float* hc = hbuf + (i & 1)*HH;
        float ar0=0.f,ar1=0.f,az0=0.f,az1=0.f,an0=0.f,an1=0.f;
        #pragma unroll
        for (int k = 0; k < HH; k += 4){
            float4 h4  = *(const float4*)(hc + k);
            float4 w4r = *(const float4*)(wr + k);
            float4 w4z = *(const float4*)(wz + k);
            float4 w4n = *(const float4*)(wn + k);
            ar0 = fmaf(h4.x,w4r.x,ar0); ar1 = fmaf(h4.y,w4r.y,ar1);
            ar0 = fmaf(h4.z,w4r.z,ar0); ar1 = fmaf(h4.w,w4r.w,ar1);
            az0 = fmaf(h4.x,w4z.x,az0); az1 = fmaf(h4.y,w4z.y,az1);
            az0 = fmaf(h4.z,w4z.z,az0); az1 = fmaf(h4.w,w4z.w,az1);
            an0 = fmaf(h4.x,w4n.x,an0); an1 = fmaf(h4.y,w4n.y,an1);
            an0 = fmaf(h4.z,w4n.z,an0); an1 = fmaf(h4.w,w4n.w,an1);
        }
        float rg = sigmoidf_(xr + bhr + ar0 + ar1);
        float zg = sigmoidf_(xz + bhz + az0 + az1);
        float ng = tanhf(xn + bhn + rg*(an0 + an1));
        float hn = (1.f - zg)*ng + zg*hself;
        hself = hn;
        hbuf[((i+1)&1)*HH + t] = hn;
        if (dir == 0) g_rh[b][i][t] = hn;
        else          g_rh[b][SS-1-i][HH+t] = hn;
        __syncthreads();
    }
}

// ---------------- K3: q[b,h,s,:] = rh[b,s,:] @ W_m[h]  (B is K-major) ----------------
__global__ __launch_bounds__(256) void k_qgemm(const float* __restrict__ wm)
{
    const int h = blockIdx.z;
    const float* W = wm + (size_t)h*H2*H2;
    __shared__ float As[16][68];
    __shared__ float Bs[16][68];
    const int tid = threadIdx.x;
    const int m0 = blockIdx.y*64, n0 = blockIdx.x*64;
    const int tr = tid>>4, tc = tid&15;
    const int la = tid>>2, lq = tid&3;
    const int lk = tid>>4, ln = tid&15;
    const float* Aflat = &g_rh[0][0][0];
    float acc[4][4] = {};
    for (int k0 = 0; k0 < H2; k0 += 16){
        float4 av = *(const float4*)(Aflat + (size_t)(m0+la)*H2 + k0 + 4*lq);
        float4 bv = *(const float4*)(W     + (size_t)(k0+lk)*H2 + n0 + 4*ln);
        __syncthreads();
        SCAT_A(av);
        *(float4*)&Bs[lk][4*ln] = bv;
        __syncthreads();
        #pragma unroll
        for (int kk2 = 0; kk2 < 16; kk2++){
            float4 a  = *(const float4*)&As[kk2][4*tr];
            float4 b4 = *(const float4*)&Bs[kk2][4*tc];
            MM16(a,b4);
        }
    }
    #pragma unroll
    for (int i = 0; i < 4; i++){
        int gm = m0 + 4*tr + i;
        int b = gm >> 10, s = gm & 1023;
        float4 o = make_float4(acc[i][0],acc[i][1],acc[i][2],acc[i][3]);
        *(float4*)&g_q[b][h][s][n0+4*tc] = o;
    }
}

// ---------------- K4: alpha[b,h,s,t] = q[b,h,s,:] . rh[b,t,:]  (B is N-major) ----------------
__global__ __launch_bounds__(256) void k_score()
{
    const int z = blockIdx.z;
    const int b = z >> 2, h = z & 3;
    __shared__ float As[16][68];
    __shared__ float Bs[16][68];
    const int tid = threadIdx.x;
    const int m0 = blockIdx.y*64, n0 = blockIdx.x*64;
    const int tr = tid>>4, tc = tid&15;
    const int la = tid>>2, lq = tid&3;
    const float* A    = &g_q[b][h][0][0];
    const float* Bsrc = &g_rh[b][0][0];
    float acc[4][4] = {};
    for (int k0 = 0; k0 < H2; k0 += 16){
        float4 av = *(const float4*)(A    + (size_t)(m0+la)*H2 + k0 + 4*lq);
        float4 bv = *(const float4*)(Bsrc + (size_t)(n0+la)*H2 + k0 + 4*lq);
        __syncthreads();
        SCAT_A(av); SCAT_B(bv);
        __syncthreads();
        #pragma unroll
        for (int kk2 = 0; kk2 < 16; kk2++){
            float4 a  = *(const float4*)&As[kk2][4*tr];
            float4 b4 = *(const float4*)&Bs[kk2][4*tc];
            MM16(a,b4);
        }
    }
    #pragma unroll
    for (int i = 0; i < 4; i++){
        int gm = m0 + 4*tr + i;
        float4 o = make_float4(acc[i][0],acc[i][1],acc[i][2],acc[i][3]);
        *(float4*)&g_alpha[b][h][gm][n0+4*tc] = o;
    }
}

// ---------------- K5: row softmax (+mask) then pre-scale by wt_w[h] ----------------
__global__ __launch_bounds__(128) void k_softmax(const float* __restrict__ mask,
                                                 const float* __restrict__ wtw)
{
    const int r = blockIdx.x*4 + (threadIdx.x >> 5);
    const int lane = threadIdx.x & 31;
    const int b = r >> 12, h = (r >> 10) & 3, s = r & 1023;
    float* ptr = &g_alpha[b][h][s][0];
    float xv[32];
    float m = -1e30f;
    #pragma unroll
    for (int c = 0; c < 32; c++){
        int t = c*32 + lane;
        float mv = mask[b*SS + t];
        float x = ptr[t] + (mv - 1.0f)*1e11f;
        xv[c] = x;
        m = fmaxf(m, x);
    }
    #pragma unroll
    for (int off = 16; off; off >>= 1) m = fmaxf(m, __shfl_xor_sync(0xffffffffu, m, off));
    float sum = 0.f;
    #pragma unroll
    for (int c = 0; c < 32; c++){
        float e = __expf(xv[c] - m);
        xv[c] = e;
        sum += e;
    }
    #pragma unroll
    for (int off = 16; off; off >>= 1) sum += __shfl_xor_sync(0xffffffffu, sum, off);
    const float scale = wtw[h] / sum;
    #pragma unroll
    for (int c = 0; c < 32; c++)
        ptr[c*32 + lane] = xv[c]*scale;
}

// ---------------- K6: out_att[b,s,:] = sum_{h,t} alpha'[b,h,s,t] * rh[b,t,:] ----------------
__global__ __launch_bounds__(256) void k_att()
{
    const int b = blockIdx.z;
    __shared__ float As[16][68];
    __shared__ float Bs[16][68];
    const int tid = threadIdx.x;
    const int m0 = blockIdx.y*64, n0 = blockIdx.x*64;
    const int tr = tid>>4, tc = tid&15;
    const int la = tid>>2, lq = tid&3;
    const int lk = tid>>4, ln = tid&15;
    float acc[4][4] = {};
    for (int k0 = 0; k0 < NHD*SS; k0 += 16){
        int h  = k0 >> 10;
        int t0 = k0 & 1023;
        float4 av = *(const float4*)(&g_alpha[b][h][m0+la][t0 + 4*lq]);
        float4 bv = *(const float4*)(&g_rh[b][t0+lk][n0 + 4*ln]);
        __syncthreads();
        SCAT_A(av);
        *(float4*)&Bs[lk][4*ln] = bv;
        __syncthreads();
        #pragma unroll
        for (int kk2 = 0; kk2 < 16; kk2++){
            float4 a  = *(const float4*)&As[kk2][4*tr];
            float4 b4 = *(const float4*)&Bs[kk2][4*tc];
            MM16(a,b4);
        }
    }
    #pragma unroll
    for (int i = 0; i < 4; i++){
        int gm = m0 + 4*tr + i;
        float4 o = make_float4(acc[i][0],acc[i][1],acc[i][2],acc[i][3]);
        *(float4*)&g_att[b][gm][n0+4*tc] = o;
    }
}

// ---------------- K7: +wt_b, project to OUT=3, log_softmax, *mask ----------------
__global__ __launch_bounds__(256) void k_out(const float* __restrict__ mask,
                                             const float* __restrict__ wtb,
                                             const float* __restrict__ wrw,
                                             const float* __restrict__ wrb,
                                             float* __restrict__ out)
{
    const int r = blockIdx.x*8 + (threadIdx.x >> 5);
    const int lane = threadIdx.x & 31;
    const float* att = &g_att[0][0][0] + (size_t)r*H2;
    const float wb0 = wtb[0];
    float v[8];
    #pragma unroll
    for (int jj = 0; jj < 8; jj++)
        v[jj] = att[jj*32 + lane] + wb0;
    float l[3];
    #pragma unroll
    for (int o = 0; o < 3; o++){
        const float* wrow = wrw + o*H2;
        float p = 0.f;
        #pragma unroll
        for (int jj = 0; jj < 8; jj++)
            p = fmaf(v[jj], wrow[jj*32 + lane], p);
        #pragma unroll
        for (int off = 16; off; off >>= 1) p += __shfl_xor_sync(0xffffffffu, p, off);
        l[o] = p + wrb[o];
    }
    if (lane == 0){
        float mx  = fmaxf(l[0], fmaxf(l[1], l[2]));
        float lse = mx + logf(__expf(l[0]-mx) + __expf(l[1]-mx) + __expf(l[2]-mx));
        float mv  = mask[r];
        out[r*3+0] = (l[0] - lse)*mv;
        out[r*3+1] = (l[1] - lse)*mv;
        out[r*3+2] = (l[2] - lse)*mv;
    }
}

// ---------------- launch ----------------
extern "C" void kernel_launch(void* const* d_in, const int* in_sizes, int n_in,
                              void* d_out, int out_size)
{
    const int*   review = (const int*)  d_in[0];
    const float* mask   = (const float*)d_in[2];
    const float* emb    = (const float*)d_in[3];
    const float* wihf   = (const float*)d_in[4];
    const float* whhf   = (const float*)d_in[5];
    const float* bihf   = (const float*)d_in[6];
    const float* bhhf   = (const float*)d_in[7];
    const float* wihb   = (const float*)d_in[8];
    const float* whhb   = (const float*)d_in[9];
    const float* bihb   = (const float*)d_in[10];
    const float* bhhb   = (const float*)d_in[11];
    const float* wm     = (const float*)d_in[12];
    const float* wtw    = (const float*)d_in[13];
    const float* wtb    = (const float*)d_in[14];
    const float* wrw    = (const float*)d_in[15];
    const float* wrb    = (const float*)d_in[16];

    const int gru_smem = (3*128*132 + 2*128) * (int)sizeof(float);  // 203776 B
    cudaFuncSetAttribute(k_gru, cudaFuncAttributeMaxDynamicSharedMemorySize, gru_smem);

    k_detect<<<1, 32>>>(review);
    k_gx<<<dim3(6, 256, 2), 256>>>(review, emb, wihf, bihf, wihb, bihb);
    k_gru<<<dim3(16, 2), 128, gru_smem>>>(whhf, bhhf, whhb, bhhb);
    k_qgemm<<<dim3(4, 256, NHD), 256>>>(wm);
    k_score<<<dim3(16, 16, BB*NHD), 256>>>();
    k_softmax<<<16384, 128>>>(mask, wtw);
    k_att<<<dim3(4, 16, BB), 256>>>();
    k_out<<<2048, 256>>>(mask, wtb, wrw, wrb, (float*)d_out);
}

// round 3
// speedup vs baseline: 1.8650x; 1.8650x over previous
#include <cuda_runtime.h>
#include <cuda_bf16.h>
#include <cstdint>
#include <math.h>

#define BB   16
#define SS   1024
#define EE   300
#define HH   128
#define H2   256
#define NHD  4
#define G3   384
#define SB   (SS*BB)   // 16384

__device__ __forceinline__ uint32_t smem_to_u32(const void* p){
    uint32_t a;
    asm("{ .reg .u64 t; cvta.to.shared.u64 t, %1; cvt.u32.u64 %0, t; }" : "=r"(a) : "l"(p));
    return a;
}
#define LDSM4(r0,r1,r2,r3,addr) \
    asm volatile("ldmatrix.sync.aligned.m8n8.x4.shared.b16 {%0,%1,%2,%3}, [%4];" \
        : "=r"(r0),"=r"(r1),"=r"(r2),"=r"(r3) : "r"(addr))

__device__ __forceinline__ void mma16816(float* c, const uint32_t* a, const uint32_t* b){
    asm volatile("mma.sync.aligned.m16n8k16.row.col.f32.bf16.bf16.f32 "
        "{%0,%1,%2,%3}, {%4,%5,%6,%7}, {%8,%9}, {%0,%1,%2,%3};"
        : "+f"(c[0]),"+f"(c[1]),"+f"(c[2]),"+f"(c[3])
        : "r"(a[0]),"r"(a[1]),"r"(a[2]),"r"(a[3]), "r"(b[0]),"r"(b[1]));
}

// ======================= scratch globals =======================
__device__ float g_gx[2][SB][G3];                       // 50 MB
__device__ float g_rh[(size_t)SB*H2];                   // [b*1024+s][256]
__device__ float g_alpha[(size_t)64*1024*1024];         // 268 MB  [(b*4+h)*1024+s][1024]
__device__ __nv_bfloat16 g_ahi[(size_t)64*1024*1024];   // 134 MB
__device__ __nv_bfloat16 g_alo[(size_t)64*1024*1024];   // 134 MB
__device__ __nv_bfloat16 g_rhhi[(size_t)SB*H2];
__device__ __nv_bfloat16 g_rhlo[(size_t)SB*H2];
__device__ __nv_bfloat16 g_rhThi[(size_t)BB*H2*SS];     // [b*256+d][1024]
__device__ __nv_bfloat16 g_rhTlo[(size_t)BB*H2*SS];
__device__ __nv_bfloat16 g_qhi[(size_t)64*1024*H2];     // [(b*4+h)*1024+s][256]
__device__ __nv_bfloat16 g_qlo[(size_t)64*1024*H2];
__device__ __nv_bfloat16 g_wmThi[(size_t)NHD*H2*H2];    // [h][e][d]
__device__ __nv_bfloat16 g_wmTlo[(size_t)NHD*H2*H2];
__device__ float g_att[(size_t)SB*H2];
__device__ int   g_is64;

__device__ __forceinline__ float sigmoidf_(float x){ return 1.0f/(1.0f+__expf(-x)); }

// ======================= detector =======================
__global__ void k_detect(const int* __restrict__ review){
    __shared__ int nz;
    if (threadIdx.x == 0) nz = 0;
    __syncthreads();
    for (int i = threadIdx.x; i < 256; i += 32)
        if (review[2*i+1] != 0) atomicAdd(&nz, 1);
    __syncthreads();
    if (threadIdx.x == 0) g_is64 = (nz == 0) ? 1 : 0;
}

// ======================= K1: gx (SIMT GEMM) =======================
#define MM16(a,b4) \
  acc[0][0]=fmaf(a.x,b4.x,acc[0][0]); acc[0][1]=fmaf(a.x,b4.y,acc[0][1]); \
  acc[0][2]=fmaf(a.x,b4.z,acc[0][2]); acc[0][3]=fmaf(a.x,b4.w,acc[0][3]); \
  acc[1][0]=fmaf(a.y,b4.x,acc[1][0]); acc[1][1]=fmaf(a.y,b4.y,acc[1][1]); \
  acc[1][2]=fmaf(a.y,b4.z,acc[1][2]); acc[1][3]=fmaf(a.y,b4.w,acc[1][3]); \
  acc[2][0]=fmaf(a.z,b4.x,acc[2][0]); acc[2][1]=fmaf(a.z,b4.y,acc[2][1]); \
  acc[2][2]=fmaf(a.z,b4.z,acc[2][2]); acc[2][3]=fmaf(a.z,b4.w,acc[2][3]); \
  acc[3][0]=fmaf(a.w,b4.x,acc[3][0]); acc[3][1]=fmaf(a.w,b4.y,acc[3][1]); \
  acc[3][2]=fmaf(a.w,b4.z,acc[3][2]); acc[3][3]=fmaf(a.w,b4.w,acc[3][3]);
#define SCAT_A(v) As[4*lq+0][la]=v.x; As[4*lq+1][la]=v.y; As[4*lq+2][la]=v.z; As[4*lq+3][la]=v.w;
#define SCAT_B(v) Bs[4*lq+0][la]=v.x; Bs[4*lq+1][la]=v.y; Bs[4*lq+2][la]=v.z; Bs[4*lq+3][la]=v.w;

__global__ __launch_bounds__(256) void k_gx(const int* __restrict__ review,
                                            const float* __restrict__ emb,
                                            const float* __restrict__ wf, const float* __restrict__ bf,
                                            const float* __restrict__ wb, const float* __restrict__ bbp)
{
    const int dir = blockIdx.z;
    const float* w    = dir ? wb  : wf;
    const float* bias = dir ? bbp : bf;
    __shared__ float As[16][68];
    __shared__ float Bs[16][68];
    __shared__ int   stok[64];
    const int tid = threadIdx.x;
    const int m0 = blockIdx.y*64, n0 = blockIdx.x*64;
    const int is64 = g_is64;
    if (tid < 64){
        int m = m0 + tid;
        int s = m >> 4, b = m & 15;
        int p = dir ? (SS-1-s) : s;
        int idx = b*SS + p;
        stok[tid] = is64 ? review[2*idx] : review[idx];
    }
    const int tr = tid>>4, tc = tid&15;
    const int la = tid>>2, lq = tid&3;
    float acc[4][4] = {};
    __syncthreads();
    const int tokla = stok[la];
    for (int k0 = 0; k0 < 304; k0 += 16){
        int kk = k0 + 4*lq;
        float4 av = make_float4(0.f,0.f,0.f,0.f);
        float4 bv = make_float4(0.f,0.f,0.f,0.f);
        if (kk < EE){
            av = *(const float4*)(emb + (size_t)tokla*EE + kk);
            bv = *(const float4*)(w   + (size_t)(n0+la)*EE + kk);
        }
        __syncthreads();
        SCAT_A(av); SCAT_B(bv);
        __syncthreads();
        #pragma unroll
        for (int kk2 = 0; kk2 < 16; kk2++){
            float4 a  = *(const float4*)&As[kk2][4*tr];
            float4 b4 = *(const float4*)&Bs[kk2][4*tc];
            MM16(a,b4);
        }
    }
    #pragma unroll
    for (int i = 0; i < 4; i++){
        int gm = m0 + 4*tr + i;
        float4 o;
        o.x = acc[i][0] + bias[n0+4*tc+0];
        o.y = acc[i][1] + bias[n0+4*tc+1];
        o.z = acc[i][2] + bias[n0+4*tc+2];
        o.w = acc[i][3] + bias[n0+4*tc+3];
        *(float4*)&g_gx[dir][gm][n0+4*tc] = o;
    }
}

// ======================= K2: GRU with register-resident weights =======================
__global__ __launch_bounds__(512,1) void k_gru(const float* __restrict__ whhf, const float* __restrict__ bhhf,
                                               const float* __restrict__ whhb, const float* __restrict__ bhhb)
{
    __shared__ float hs[2*HH];
    const int b = blockIdx.x, dir = blockIdx.y;
    const float* whh = dir ? whhb : whhf;
    const float* bhh = dir ? bhhb : bhhf;
    const int tid = threadIdx.x;
    const int w = tid >> 5, l = tid & 31;
    const int n = w*8 + (l & 7);
    const int sl = l >> 3;
    const int r  = l & 7;

    float4 wg[3][8];
    #pragma unroll
    for (int g = 0; g < 3; g++){
        const float* wrow = whh + (size_t)(g*HH + n)*HH + sl*32;
        #pragma unroll
        for (int j = 0; j < 8; j++){
            int ko = ((j + r) & 7) * 4;
            wg[g][j] = *(const float4*)(wrow + ko);
        }
    }
    const float bhr = bhh[n], bhz = bhh[HH+n], bhn = bhh[2*HH+n];
    if (tid < 2*HH) hs[tid] = 0.f;
    const float* gxbase = &g_gx[dir][0][0] + b*G3;
    float hself = 0.f;
    float xr = gxbase[n], xz = gxbase[HH+n], xn = gxbase[2*HH+n];
    __syncthreads();

    for (int i = 0; i < SS; i++){
        float xr2 = 0.f, xz2 = 0.f, xn2 = 0.f;
        if (i + 1 < SS){
            const float* g2 = gxbase + (size_t)(i+1)*(BB*G3);
            xr2 = g2[n]; xz2 = g2[HH+n]; xn2 = g2[2*HH+n];
        }
        const float* hc = hs + (i & 1)*HH + sl*32;
        float ar = 0.f, az = 0.f, an = 0.f;
        #pragma unroll
        for (int j = 0; j < 8; j++){
            float4 h4 = *(const float4*)(hc + ((j + r) & 7)*4);
            ar = fmaf(h4.x, wg[0][j].x, ar); ar = fmaf(h4.y, wg[0][j].y, ar);
            ar = fmaf(h4.z, wg[0][j].z, ar); ar = fmaf(h4.w, wg[0][j].w, ar);
            az = fmaf(h4.x, wg[1][j].x, az); az = fmaf(h4.y, wg[1][j].y, az);
            az = fmaf(h4.z, wg[1][j].z, az); az = fmaf(h4.w, wg[1][j].w, az);
            an = fmaf(h4.x, wg[2][j].x, an); an = fmaf(h4.y, wg[2][j].y, an);
            an = fmaf(h4.z, wg[2][j].z, an); an = fmaf(h4.w, wg[2][j].w, an);
        }
        ar += __shfl_xor_sync(0xffffffffu, ar, 8);  ar += __shfl_xor_sync(0xffffffffu, ar, 16);
        az += __shfl_xor_sync(0xffffffffu, az, 8);  az += __shfl_xor_sync(0xffffffffu, az, 16);
        an += __shfl_xor_sync(0xffffffffu, an, 8);  an += __shfl_xor_sync(0xffffffffu, an, 16);
        float rg = sigmoidf_(xr + bhr + ar);
        float zg = sigmoidf_(xz + bhz + az);
        float ng = tanhf(xn + bhn + rg*an);
        float hn = (1.f - zg)*ng + zg*hself;
        hself = hn;
        if (sl == 0){
            hs[((i+1) & 1)*HH + n] = hn;
            int pos = dir ? (SS-1-i) : i;
            int col = dir ? (HH + n) : n;
            size_t ro = ((size_t)b*SS + pos)*H2 + col;
            g_rh[ro] = hn;
            __nv_bfloat16 h16 = __float2bfloat16(hn);
            g_rhhi[ro] = h16;
            g_rhlo[ro] = __float2bfloat16(hn - __bfloat162float(h16));
        }
        xr = xr2; xz = xz2; xn = xn2;
        __syncthreads();
    }
}

// ======================= transposes + split conversion =======================
__global__ void k_rhT(){
    __shared__ float t[32][33];
    const int b = blockIdx.z, s0 = blockIdx.x*32, d0 = blockIdx.y*32;
    const int tx = threadIdx.x, ty = threadIdx.y;
    #pragma unroll
    for (int k = 0; k < 32; k += 8)
        t[ty+k][tx] = g_rh[((size_t)b*SS + s0+ty+k)*H2 + d0+tx];
    __syncthreads();
    #pragma unroll
    for (int k = 0; k < 32; k += 8){
        float v = t[tx][ty+k];
        __nv_bfloat16 h = __float2bfloat16(v);
        size_t o = ((size_t)b*H2 + d0+ty+k)*SS + s0+tx;
        g_rhThi[o] = h;
        g_rhTlo[o] = __float2bfloat16(v - __bfloat162float(h));
    }
}

__global__ void k_wmT(const float* __restrict__ wm){
    __shared__ float t[32][33];
    const int h = blockIdx.z, d0 = blockIdx.x*32, e0 = blockIdx.y*32;
    const int tx = threadIdx.x, ty = threadIdx.y;
    #pragma unroll
    for (int k = 0; k < 32; k += 8)
        t[ty+k][tx] = wm[((size_t)h*H2 + d0+ty+k)*H2 + e0+tx];
    __syncthreads();
    #pragma unroll
    for (int k = 0; k < 32; k += 8){
        float v = t[tx][ty+k];
        __nv_bfloat16 hh = __float2bfloat16(v);
        size_t o = ((size_t)h*H2 + e0+ty+k)*H2 + d0+tx;
        g_wmThi[o] = hh;
        g_wmTlo[o] = __float2bfloat16(v - __bfloat162float(hh));
    }
}

// ======================= unified split-bf16 mma.sync GEMM =======================
#define TROW 144
#define TSZ  (128*TROW)
#define MMASM (4*TSZ)

__device__ __forceinline__ void stage64p(const __nv_bfloat16* __restrict__ src, int ld, char* dst, int tid){
    #pragma unroll
    for (int it = 0; it < 4; it++){
        int i = it*256 + tid;
        int row = i >> 3, c8 = i & 7;
        uint4 v = *(const uint4*)(src + (size_t)row*ld + c8*8);
        *(uint4*)(dst + row*TROW + c8*16) = v;
    }
}

template<int MODE, int KTOT>
__global__ __launch_bounds__(256,1) void k_mma()
{
    extern __shared__ char sm[];
    const uint32_t smb = smem_to_u32(sm);
    const int tid = threadIdx.x;
    const int wid = tid >> 5, lane = tid & 31;
    const int n0 = blockIdx.x*128, m0 = blockIdx.y*128, z = blockIdx.z;
    const int m0w = (wid & 1)*64, n0w = (wid >> 1)*32;

    const __nv_bfloat16 *AH, *AL, *BH, *BL;
    if constexpr (MODE == 0){ AH = g_rhhi; AL = g_rhlo; BH = g_wmThi; BL = g_wmTlo; }
    else if constexpr (MODE == 1){ AH = g_qhi; AL = g_qlo; BH = g_rhhi; BL = g_rhlo; }
    else { AH = g_ahi; AL = g_alo; BH = g_rhThi; BL = g_rhTlo; }

    float acc[4][4][4] = {};
    const int arow = lane & 15;
    const uint32_t acolb = ((lane >> 4) << 4);

    for (int c = 0; c < KTOT/64; c++){
        const int kb = c*64;
        size_t aoff, boff; int lda, ldb;
        if constexpr (MODE == 0){
            aoff = (size_t)m0*H2 + kb;                     lda = H2;
            boff = ((size_t)z*H2 + n0)*H2 + kb;            ldb = H2;
        } else if constexpr (MODE == 1){
            aoff = ((size_t)z*SS + m0)*H2 + kb;            lda = H2;
            boff = ((size_t)(z>>2)*SS + n0)*H2 + kb;       ldb = H2;
        } else {
            const int hh = kb >> 10, t0 = kb & 1023;
            aoff = (((size_t)z*NHD + hh)*SS + m0)*SS + t0; lda = SS;
            boff = ((size_t)z*H2 + n0)*SS + t0;            ldb = SS;
        }
        if (c) __syncthreads();
        stage64p(AH + aoff, lda, sm,         tid);
        stage64p(AL + aoff, lda, sm + TSZ,   tid);
        stage64p(BH + boff, ldb, sm + 2*TSZ, tid);
        stage64p(BL + boff, ldb, sm + 3*TSZ, tid);
        __syncthreads();

        #pragma unroll
        for (int ks = 0; ks < 4; ks++){
            const uint32_t kbyte = ks*32 + acolb;
            uint32_t ah[4][4], al[4][4], bh[4][2], bl[4][2];
            #pragma unroll
            for (int mf = 0; mf < 4; mf++){
                uint32_t ra = smb + (m0w + mf*16 + arow)*TROW + kbyte;
                LDSM4(ah[mf][0], ah[mf][1], ah[mf][2], ah[mf][3], ra);
                LDSM4(al[mf][0], al[mf][1], al[mf][2], al[mf][3], ra + TSZ);
            }
            #pragma unroll
            for (int nf2 = 0; nf2 < 2; nf2++){
                uint32_t rb = smb + 2*TSZ + (n0w + nf2*16 + arow)*TROW + kbyte;
                uint32_t r0,r1,r2,r3;
                LDSM4(r0,r1,r2,r3, rb);
                bh[2*nf2][0]=r0; bh[2*nf2][1]=r2; bh[2*nf2+1][0]=r1; bh[2*nf2+1][1]=r3;
                LDSM4(r0,r1,r2,r3, rb + TSZ);
                bl[2*nf2][0]=r0; bl[2*nf2][1]=r2; bl[2*nf2+1][0]=r1; bl[2*nf2+1][1]=r3;
            }
            #pragma unroll
            for (int mf = 0; mf < 4; mf++)
                #pragma unroll
                for (int nf = 0; nf < 4; nf++){
                    mma16816(acc[mf][nf], ah[mf], bh[nf]);
                    mma16816(acc[mf][nf], al[mf], bh[nf]);
                    mma16816(acc[mf][nf], ah[mf], bl[nf]);
                }
        }
    }

    const int erow = lane >> 2;
    const int ecol = 2*(lane & 3);
    #pragma unroll
    for (int mf = 0; mf < 4; mf++){
        #pragma unroll
        for (int nf = 0; nf < 4; nf++){
            int rrow = m0 + m0w + mf*16 + erow;
            int ccol = n0 + n0w + nf*8 + ecol;
            if constexpr (MODE == 1){
                float* o = g_alpha + ((size_t)z*SS + rrow)*SS + ccol;
                *(float2*)o          = make_float2(acc[mf][nf][0], acc[mf][nf][1]);
                *(float2*)(o + 8*SS) = make_float2(acc[mf][nf][2], acc[mf][nf][3]);
            } else if constexpr (MODE == 2){
                float* o = g_att + ((size_t)z*SS + rrow)*H2 + ccol;
                *(float2*)o          = make_float2(acc[mf][nf][0], acc[mf][nf][1]);
                *(float2*)(o + 8*H2) = make_float2(acc[mf][nf][2], acc[mf][nf][3]);
            } else {
                #pragma unroll
                for (int half = 0; half < 2; half++){
                    int gm = rrow + half*8;
                    int b = gm >> 10, s = gm & 1023;
                    size_t o = (((size_t)b*NHD + z)*SS + s)*H2 + ccol;
                    float v0 = acc[mf][nf][2*half], v1 = acc[mf][nf][2*half+1];
                    __nv_bfloat16 h0 = __float2bfloat16(v0);
                    __nv_bfloat16 h1 = __float2bfloat16(v1);
                    *(__nv_bfloat162*)(g_qhi + o) = __nv_bfloat162(h0, h1);
                    *(__nv_bfloat162*)(g_qlo + o) = __nv_bfloat162(
                        __float2bfloat16(v0 - __bfloat162float(h0)),
                        __float2bfloat16(v1 - __bfloat162float(h1)));
                }
            }
        }
    }
}

// ======================= K5: softmax -> split bf16 alpha, pre-scaled by wt_w[h] =======================
__global__ __launch_bounds__(128) void k_softmax(const float* __restrict__ mask,
                                                 const float* __restrict__ wtw)
{
    const int rr = blockIdx.x*4 + (threadIdx.x >> 5);
    const int lane = threadIdx.x & 31;
    const int b = rr >> 12, h = (rr >> 10) & 3;
    const float* ptr = g_alpha + (size_t)rr*SS;
    float xv[32];
    float m = -1e30f;
    #pragma unroll
    for (int c = 0; c < 32; c++){
        int t = c*32 + lane;
        float mv = mask[b*SS + t];
        float x = ptr[t] + (mv - 1.0f)*1e11f;
        xv[c] = x;
        m = fmaxf(m, x);
    }
    #pragma unroll
    for (int off = 16; off; off >>= 1) m = fmaxf(m, __shfl_xor_sync(0xffffffffu, m, off));
    float sum = 0.f;
    #pragma unroll
    for (int c = 0; c < 32; c++){
        float e = __expf(xv[c] - m);
        xv[c] = e;
        sum += e;
    }
    #pragma unroll
    for (int off = 16; off; off >>= 1) sum += __shfl_xor_sync(0xffffffffu, sum, off);
    const float scale = wtw[h] / sum;
    __nv_bfloat16* oh = g_ahi + (size_t)rr*SS;
    __nv_bfloat16* ol = g_alo + (size_t)rr*SS;
    #pragma unroll
    for (int c = 0; c < 32; c++){
        float v = xv[c]*scale;
        __nv_bfloat16 hi = __float2bfloat16(v);
        oh[c*32 + lane] = hi;
        ol[c*32 + lane] = __float2bfloat16(v - __bfloat162float(hi));
    }
}

// ======================= K7 =======================
__global__ __launch_bounds__(256) void k_out(const float* __restrict__ mask,
                                             const float* __restrict__ wtb,
                                             const float* __restrict__ wrw,
                                             const float* __restrict__ wrb,
                                             float* __restrict__ out)
{
    const int rr = blockIdx.x*8 + (threadIdx.x >> 5);
    const int lane = threadIdx.x & 31;
    const float* att = g_att + (size_t)rr*H2;
    const float wb0 = wtb[0];
    float v[8];
    #pragma unroll
    for (int jj = 0; jj < 8; jj++)
        v[jj] = att[jj*32 + lane] + wb0;
    float l[3];
    #pragma unroll
    for (int o = 0; o < 3; o++){
        const float* wrow = wrw + o*H2;
        float p = 0.f;
        #pragma unroll
        for (int jj = 0; jj < 8; jj++)
            p = fmaf(v[jj], wrow[jj*32 + lane], p);
        #pragma unroll
        for (int off = 16; off; off >>= 1) p += __shfl_xor_sync(0xffffffffu, p, off);
        l[o] = p + wrb[o];
    }
    if (lane == 0){
        float mx  = fmaxf(l[0], fmaxf(l[1], l[2]));
        float lse = mx + logf(__expf(l[0]-mx) + __expf(l[1]-mx) + __expf(l[2]-mx));
        float mv  = mask[rr];
        out[rr*3+0] = (l[0] - lse)*mv;
        out[rr*3+1] = (l[1] - lse)*mv;
        out[rr*3+2] = (l[2] - lse)*mv;
    }
}

// ======================= launch =======================
extern "C" void kernel_launch(void* const* d_in, const int* in_sizes, int n_in,
                              void* d_out, int out_size)
{
    const int*   review = (const int*)  d_in[0];
    const float* mask   = (const float*)d_in[2];
    const float* emb    = (const float*)d_in[3];
    const float* wihf   = (const float*)d_in[4];
    const float* whhf   = (const float*)d_in[5];
    const float* bihf   = (const float*)d_in[6];
    const float* bhhf   = (const float*)d_in[7];
    const float* wihb   = (const float*)d_in[8];
    const float* whhb   = (const float*)d_in[9];
    const float* bihb   = (const float*)d_in[10];
    const float* bhhb   = (const float*)d_in[11];
    const float* wm     = (const float*)d_in[12];
    const float* wtw    = (const float*)d_in[13];
    const float* wtb    = (const float*)d_in[14];
    const float* wrw    = (const float*)d_in[15];
    const float* wrb    = (const float*)d_in[16];

    cudaFuncSetAttribute(k_mma<0,256>,  cudaFuncAttributeMaxDynamicSharedMemorySize, MMASM);
    cudaFuncSetAttribute(k_mma<1,256>,  cudaFuncAttributeMaxDynamicSharedMemorySize, MMASM);
    cudaFuncSetAttribute(k_mma<2,4096>, cudaFuncAttributeMaxDynamicSharedMemorySize, MMASM);

    k_detect<<<1, 32>>>(review);
    k_gx<<<dim3(6, 256, 2), 256>>>(review, emb, wihf, bihf, wihb, bihb);
    k_wmT<<<dim3(8, 8, 4), dim3(32, 8)>>>(wm);
    k_gru<<<dim3(16, 2), 512>>>(whhf, bhhf, whhb, bhhb);
    k_rhT<<<dim3(32, 8, 16), dim3(32, 8)>>>();
    k_mma<0,256><<<dim3(2, 128, 4),  256, MMASM>>>();   // q
    k_mma<1,256><<<dim3(8, 8, 64),   256, MMASM>>>();   // scores
    k_softmax<<<16384, 128>>>(mask, wtw);
    k_mma<2,4096><<<dim3(2, 8, 16),  256, MMASM>>>();   // att
    k_out<<<2048, 256>>>(mask, wtb, wrw, wrb, (float*)d_out);
}

// round 4
// speedup vs baseline: 2.0231x; 1.0848x over previous
#include <cuda_runtime.h>
#include <cuda_bf16.h>
#include <cstdint>
#include <math.h>

#define BB   16
#define SS   1024
#define EE   300
#define EP   320
#define HH   128
#define H2   256
#define NHD  4
#define G3   384
#define SB   (SS*BB)   // 16384

typedef unsigned long long u64;

__device__ __forceinline__ uint32_t smem_to_u32(const void* p){
    uint32_t a;
    asm("{ .reg .u64 t; cvta.to.shared.u64 t, %1; cvt.u32.u64 %0, t; }" : "=r"(a) : "l"(p));
    return a;
}
#define LDSM4(r0,r1,r2,r3,addr) \
    asm volatile("ldmatrix.sync.aligned.m8n8.x4.shared.b16 {%0,%1,%2,%3}, [%4];" \
        : "=r"(r0),"=r"(r1),"=r"(r2),"=r"(r3) : "r"(addr))

__device__ __forceinline__ void mma16816(float* c, const uint32_t* a, const uint32_t* b){
    asm volatile("mma.sync.aligned.m16n8k16.row.col.f32.bf16.bf16.f32 "
        "{%0,%1,%2,%3}, {%4,%5,%6,%7}, {%8,%9}, {%0,%1,%2,%3};"
        : "+f"(c[0]),"+f"(c[1]),"+f"(c[2]),"+f"(c[3])
        : "r"(a[0]),"r"(a[1]),"r"(a[2]),"r"(a[3]), "r"(b[0]),"r"(b[1]));
}
__device__ __forceinline__ u64 fma_x2(u64 a, u64 b, u64 c){
    u64 d; asm("fma.rn.f32x2 %0, %1, %2, %3;" : "=l"(d) : "l"(a), "l"(b), "l"(c)); return d;
}
__device__ __forceinline__ float tanh_fast(float x){
    float y; asm("tanh.approx.f32 %0, %1;" : "=f"(y) : "f"(x)); return y;
}
__device__ __forceinline__ float sigmoid_fast(float x){
    return __fdividef(1.0f, 1.0f + __expf(-x));
}
__device__ __forceinline__ float lo_of(u64 p){ return __uint_as_float((uint32_t)p); }
__device__ __forceinline__ float hi_of(u64 p){ return __uint_as_float((uint32_t)(p >> 32)); }

// ======================= scratch globals =======================
__device__ float g_gx[2][SB][G3];                       // 50 MB
__device__ float g_rh[(size_t)SB*H2];                   // [b*1024+s][256]
__device__ float g_alpha[(size_t)64*1024*1024];         // 268 MB  [(b*4+h)*1024+s][1024]
__device__ __nv_bfloat16 g_ahi[(size_t)64*1024*1024];
__device__ __nv_bfloat16 g_alo[(size_t)64*1024*1024];
__device__ __nv_bfloat16 g_rhhi[(size_t)SB*H2];
__device__ __nv_bfloat16 g_rhlo[(size_t)SB*H2];
__device__ __nv_bfloat16 g_rhThi[(size_t)BB*H2*SS];     // [b*256+d][1024]
__device__ __nv_bfloat16 g_rhTlo[(size_t)BB*H2*SS];
__device__ __nv_bfloat16 g_qhi[(size_t)64*1024*H2];     // [(b*4+h)*1024+s][256]
__device__ __nv_bfloat16 g_qlo[(size_t)64*1024*H2];
__device__ __nv_bfloat16 g_wmThi[(size_t)NHD*H2*H2];    // [h][e][d]
__device__ __nv_bfloat16 g_wmTlo[(size_t)NHD*H2*H2];
__device__ __nv_bfloat16 g_embhi[(size_t)32000*EP];     // 20.5 MB, zero-padded to 320
__device__ __nv_bfloat16 g_emblo[(size_t)32000*EP];
__device__ __nv_bfloat16 g_wihhi[(size_t)2*G3*EP];      // [dir][n][320]
__device__ __nv_bfloat16 g_wihlo[(size_t)2*G3*EP];
__device__ float g_att[(size_t)SB*H2];
__device__ int   g_is64;

// ======================= detector =======================
__global__ void k_detect(const int* __restrict__ review){
    __shared__ int nz;
    if (threadIdx.x == 0) nz = 0;
    __syncthreads();
    for (int i = threadIdx.x; i < 256; i += 32)
        if (review[2*i+1] != 0) atomicAdd(&nz, 1);
    __syncthreads();
    if (threadIdx.x == 0) g_is64 = (nz == 0) ? 1 : 0;
}

// ======================= conversions =======================
__global__ void k_embcvt(const float* __restrict__ emb){
    const int row = blockIdx.x;
    for (int c = threadIdx.x; c < EP; c += 256){
        float v = (c < EE) ? emb[(size_t)row*EE + c] : 0.f;
        __nv_bfloat16 h = __float2bfloat16(v);
        size_t o = (size_t)row*EP + c;
        g_embhi[o] = h;
        g_emblo[o] = __float2bfloat16(v - __bfloat162float(h));
    }
}
__global__ void k_wihcvt(const float* __restrict__ wf, const float* __restrict__ wb){
    const int dir = blockIdx.y, n = blockIdx.x;
    const float* w = dir ? wb : wf;
    for (int c = threadIdx.x; c < EP; c += 256){
        float v = (c < EE) ? w[(size_t)n*EE + c] : 0.f;
        __nv_bfloat16 h = __float2bfloat16(v);
        size_t o = ((size_t)dir*G3 + n)*EP + c;
        g_wihhi[o] = h;
        g_wihlo[o] = __float2bfloat16(v - __bfloat162float(h));
    }
}
__global__ void k_wmT(const float* __restrict__ wm){
    __shared__ float t[32][33];
    const int h = blockIdx.z, d0 = blockIdx.x*32, e0 = blockIdx.y*32;
    const int tx = threadIdx.x, ty = threadIdx.y;
    #pragma unroll
    for (int k = 0; k < 32; k += 8)
        t[ty+k][tx] = wm[((size_t)h*H2 + d0+ty+k)*H2 + e0+tx];
    __syncthreads();
    #pragma unroll
    for (int k = 0; k < 32; k += 8){
        float v = t[tx][ty+k];
        __nv_bfloat16 hh = __float2bfloat16(v);
        size_t o = ((size_t)h*H2 + e0+ty+k)*H2 + d0+tx;
        g_wmThi[o] = hh;
        g_wmTlo[o] = __float2bfloat16(v - __bfloat162float(hh));
    }
}

// ======================= GRU: packed f32x2 FMA, register weights =======================
__global__ __launch_bounds__(512,1) void k_gru(const float* __restrict__ whhf, const float* __restrict__ bhhf,
                                               const float* __restrict__ whhb, const float* __restrict__ bhhb)
{
    __shared__ __align__(16) float hs[2*HH];
    const int b = blockIdx.x, dir = blockIdx.y;
    const float* whh = dir ? whhb : whhf;
    const float* bhh = dir ? bhhb : bhhf;
    const int tid = threadIdx.x;
    const int w = tid >> 5, l = tid & 31;
    const int n = w*8 + (l & 7);
    const int sl = l >> 3;
    const int r  = l & 7;

    // weights as packed f32x2 pairs, rotated by r
    ulonglong2 wg2[3][8];
    #pragma unroll
    for (int g = 0; g < 3; g++){
        const ulonglong2* wrow = (const ulonglong2*)(whh + (size_t)(g*HH + n)*HH + sl*32);
        #pragma unroll
        for (int j = 0; j < 8; j++)
            wg2[g][j] = wrow[(j + r) & 7];
    }
    const float bhr = bhh[n], bhz = bhh[HH+n], bhn = bhh[2*HH+n];
    if (tid < 2*HH) hs[tid] = 0.f;
    const float* gxbase = &g_gx[dir][0][0] + b*G3;
    float hself = 0.f;
    float xr = gxbase[n], xz = gxbase[HH+n], xn = gxbase[2*HH+n];
    __syncthreads();

    for (int i = 0; i < SS; i++){
        float xr2 = 0.f, xz2 = 0.f, xn2 = 0.f;
        if (i + 1 < SS){
            const float* g2 = gxbase + (size_t)(i+1)*(BB*G3);
            xr2 = g2[n]; xz2 = g2[HH+n]; xn2 = g2[2*HH+n];
        }
        const ulonglong2* hc2 = (const ulonglong2*)(hs + (i & 1)*HH + sl*32);
        u64 pr = 0ull, pz = 0ull, pn = 0ull;
        #pragma unroll
        for (int j = 0; j < 8; j++){
            ulonglong2 h2 = hc2[(j + r) & 7];
            pr = fma_x2(h2.x, wg2[0][j].x, pr); pr = fma_x2(h2.y, wg2[0][j].y, pr);
            pz = fma_x2(h2.x, wg2[1][j].x, pz); pz = fma_x2(h2.y, wg2[1][j].y, pz);
            pn = fma_x2(h2.x, wg2[2][j].x, pn); pn = fma_x2(h2.y, wg2[2][j].y, pn);
        }
        float ar = lo_of(pr) + hi_of(pr);
        float az = lo_of(pz) + hi_of(pz);
        float an = lo_of(pn) + hi_of(pn);
        ar += __shfl_xor_sync(0xffffffffu, ar, 8);  ar += __shfl_xor_sync(0xffffffffu, ar, 16);
        az += __shfl_xor_sync(0xffffffffu, az, 8);  az += __shfl_xor_sync(0xffffffffu, az, 16);
        an += __shfl_xor_sync(0xffffffffu, an, 8);  an += __shfl_xor_sync(0xffffffffu, an, 16);
        float rg = sigmoid_fast(xr + bhr + ar);
        float zg = sigmoid_fast(xz + bhz + az);
        float ng = tanh_fast(xn + bhn + rg*an);
        float hn = (1.f - zg)*ng + zg*hself;
        hself = hn;
        if (sl == 0){
            hs[((i+1) & 1)*HH + n] = hn;
            int pos = dir ? (SS-1-i) : i;
            int col = dir ? (HH + n) : n;
            size_t ro = ((size_t)b*SS + pos)*H2 + col;
            g_rh[ro] = hn;
            __nv_bfloat16 h16 = __float2bfloat16(hn);
            g_rhhi[ro] = h16;
            g_rhlo[ro] = __float2bfloat16(hn - __bfloat162float(h16));
        }
        xr = xr2; xz = xz2; xn = xn2;
        __syncthreads();
    }
}

// ======================= rh transpose =======================
__global__ void k_rhT(){
    __shared__ float t[32][33];
    const int b = blockIdx.z, s0 = blockIdx.x*32, d0 = blockIdx.y*32;
    const int tx = threadIdx.x, ty = threadIdx.y;
    #pragma unroll
    for (int k = 0; k < 32; k += 8)
        t[ty+k][tx] = g_rh[((size_t)b*SS + s0+ty+k)*H2 + d0+tx];
    __syncthreads();
    #pragma unroll
    for (int k = 0; k < 32; k += 8){
        float v = t[tx][ty+k];
        __nv_bfloat16 h = __float2bfloat16(v);
        size_t o = ((size_t)b*H2 + d0+ty+k)*SS + s0+tx;
        g_rhThi[o] = h;
        g_rhTlo[o] = __float2bfloat16(v - __bfloat162float(h));
    }
}

// ======================= unified split-bf16 mma.sync GEMM =======================
// MODE 0: q = rh @ wmT        (z = h,     K=256,  epi -> qhi/qlo)
// MODE 1: alpha = q @ rh^T    (z = b*4+h, K=256,  epi -> fp32 g_alpha)
// MODE 2: att = alpha' @ rh   (z = b,     K=4096, epi -> fp32 g_att)
// MODE 3: gx = emb[tok] @ wih^T + b  (z = dir, K=320, N=384, epi -> fp32 g_gx)
#define TROW 144
#define TSZ  (128*TROW)
#define MMASM (4*TSZ)

__device__ __forceinline__ void stage64p(const __nv_bfloat16* __restrict__ src, int ld, char* dst, int tid){
    #pragma unroll
    for (int it = 0; it < 4; it++){
        int i = it*256 + tid;
        int row = i >> 3, c8 = i & 7;
        uint4 v = *(const uint4*)(src + (size_t)row*ld + c8*8);
        *(uint4*)(dst + row*TROW + c8*16) = v;
    }
}

template<int MODE, int KTOT>
__global__ __launch_bounds__(256,1) void k_mma(const int* __restrict__ review,
                                               const float* __restrict__ bias_f,
                                               const float* __restrict__ bias_b)
{
    extern __shared__ char sm[];
    __shared__ int stok[128];
    const uint32_t smb = smem_to_u32(sm);
    const int tid = threadIdx.x;
    const int wid = tid >> 5, lane = tid & 31;
    const int n0 = blockIdx.x*128, m0 = blockIdx.y*128, z = blockIdx.z;
    const int m0w = (wid & 1)*64, n0w = (wid >> 1)*32;

    const __nv_bfloat16 *AH, *AL, *BH, *BL;
    if constexpr (MODE == 0){ AH = g_rhhi; AL = g_rhlo; BH = g_wmThi; BL = g_wmTlo; }
    else if constexpr (MODE == 1){ AH = g_qhi; AL = g_qlo; BH = g_rhhi; BL = g_rhlo; }
    else if constexpr (MODE == 2){ AH = g_ahi; AL = g_alo; BH = g_rhThi; BL = g_rhTlo; }
    else { AH = g_embhi; AL = g_emblo; BH = g_wihhi; BL = g_wihlo; }

    if constexpr (MODE == 3){
        const int is64 = g_is64;
        if (tid < 128){
            int m = m0 + tid;
            int s = m >> 4, b = m & 15;
            int p = z ? (SS-1-s) : s;
            int idx = b*SS + p;
            stok[tid] = is64 ? review[2*idx] : review[idx];
        }
        __syncthreads();
    }

    float acc[4][4][4] = {};
    const int arow = lane & 15;
    const uint32_t acolb = ((lane >> 4) << 4);

    for (int c = 0; c < KTOT/64; c++){
        const int kb = c*64;
        if (c) __syncthreads();
        if constexpr (MODE == 3){
            #pragma unroll
            for (int it = 0; it < 4; it++){
                int i = it*256 + tid;
                int row = i >> 3, c8 = i & 7;
                size_t so = (size_t)stok[row]*EP + kb + c8*8;
                *(uint4*)(sm +       row*TROW + c8*16) = *(const uint4*)(AH + so);
                *(uint4*)(sm + TSZ + row*TROW + c8*16) = *(const uint4*)(AL + so);
            }
            size_t boff = ((size_t)z*G3 + n0)*EP + kb;
            stage64p(BH + boff, EP, sm + 2*TSZ, tid);
            stage64p(BL + boff, EP, sm + 3*TSZ, tid);
        } else {
            size_t aoff, boff; int lda, ldb;
            if constexpr (MODE == 0){
                aoff = (size_t)m0*H2 + kb;                     lda = H2;
                boff = ((size_t)z*H2 + n0)*H2 + kb;            ldb = H2;
            } else if constexpr (MODE == 1){
                aoff = ((size_t)z*SS + m0)*H2 + kb;            lda = H2;
                boff = ((size_t)(z>>2)*SS + n0)*H2 + kb;       ldb = H2;
            } else {
                const int hh = kb >> 10, t0 = kb & 1023;
                aoff = (((size_t)z*NHD + hh)*SS + m0)*SS + t0; lda = SS;
                boff = ((size_t)z*H2 + n0)*SS + t0;            ldb = SS;
            }
            stage64p(AH + aoff, lda, sm,         tid);
            stage64p(AL + aoff, lda, sm + TSZ,   tid);
            stage64p(BH + boff, ldb, sm + 2*TSZ, tid);
            stage64p(BL + boff, ldb, sm + 3*TSZ, tid);
        }
        __syncthreads();

        #pragma unroll
        for (int ks = 0; ks < 4; ks++){
            const uint32_t kbyte = ks*32 + acolb;
            uint32_t ah[4][4], al[4][4], bh[4][2], bl[4][2];
            #pragma unroll
            for (int mf = 0; mf < 4; mf++){
                uint32_t ra = smb + (m0w + mf*16 + arow)*TROW + kbyte;
                LDSM4(ah[mf][0], ah[mf][1], ah[mf][2], ah[mf][3], ra);
                LDSM4(al[mf][0], al[mf][1], al[mf][2], al[mf][3], ra + TSZ);
            }
            #pragma unroll
            for (int nf2 = 0; nf2 < 2; nf2++){
                uint32_t rb = smb + 2*TSZ + (n0w + nf2*16 + arow)*TROW + kbyte;
                uint32_t r0,r1,r2,r3;
                LDSM4(r0,r1,r2,r3, rb);
                bh[2*nf2][0]=r0; bh[2*nf2][1]=r2; bh[2*nf2+1][0]=r1; bh[2*nf2+1][1]=r3;
                LDSM4(r0,r1,r2,r3, rb + TSZ);
                bl[2*nf2][0]=r0; bl[2*nf2][1]=r2; bl[2*nf2+1][0]=r1; bl[2*nf2+1][1]=r3;
            }
            #pragma unroll
            for (int mf = 0; mf < 4; mf++)
                #pragma unroll
                for (int nf = 0; nf < 4; nf++){
                    mma16816(acc[mf][nf], ah[mf], bh[nf]);
                    mma16816(acc[mf][nf], al[mf], bh[nf]);
                    mma16816(acc[mf][nf], ah[mf], bl[nf]);
                }
        }
    }

    const int erow = lane >> 2;
    const int ecol = 2*(lane & 3);
    #pragma unroll
    for (int mf = 0; mf < 4; mf++){
        #pragma unroll
        for (int nf = 0; nf < 4; nf++){
            int rrow = m0 + m0w + mf*16 + erow;
            int ccol = n0 + n0w + nf*8 + ecol;
            if constexpr (MODE == 1){
                float* o = g_alpha + ((size_t)z*SS + rrow)*SS + ccol;
                *(float2*)o          = make_float2(acc[mf][nf][0], acc[mf][nf][1]);
                *(float2*)(o + 8*SS) = make_float2(acc[mf][nf][2], acc[mf][nf][3]);
            } else if constexpr (MODE == 2){
                float* o = g_att + ((size_t)z*SS + rrow)*H2 + ccol;
                *(float2*)o          = make_float2(acc[mf][nf][0], acc[mf][nf][1]);
                *(float2*)(o + 8*H2) = make_float2(acc[mf][nf][2], acc[mf][nf][3]);
            } else if constexpr (MODE == 3){
                const float* bias = z ? bias_b : bias_f;
                float b0 = bias[ccol], b1 = bias[ccol+1];
                float* o = &g_gx[z][rrow][ccol];
                *(float2*)o          = make_float2(acc[mf][nf][0]+b0, acc[mf][nf][1]+b1);
                *(float2*)(o + 8*G3) = make_float2(acc[mf][nf][2]+b0, acc[mf][nf][3]+b1);
            } else {
                #pragma unroll
                for (int half = 0; half < 2; half++){
                    int gm = rrow + half*8;
                    int b = gm >> 10, s = gm & 1023;
                    size_t o = (((size_t)b*NHD + z)*SS + s)*H2 + ccol;
                    float v0 = acc[mf][nf][2*half], v1 = acc[mf][nf][2*half+1];
                    __nv_bfloat16 h0 = __float2bfloat16(v0);
                    __nv_bfloat16 h1 = __float2bfloat16(v1);
                    *(__nv_bfloat162*)(g_qhi + o) = __nv_bfloat162(h0, h1);
                    *(__nv_bfloat162*)(g_qlo + o) = __nv_bfloat162(
                        __float2bfloat16(v0 - __bfloat162float(h0)),
                        __float2bfloat16(v1 - __bfloat162float(h1)));
                }
            }
        }
    }
}

// ======================= K5: softmax -> split bf16 alpha, pre-scaled by wt_w[h] =======================
__global__ __launch_bounds__(128) void k_softmax(const float* __restrict__ mask,
                                                 const float* __restrict__ wtw)
{
    const int rr = blockIdx.x*4 + (threadIdx.x >> 5);
    const int lane = threadIdx.x & 31;
    const int b = rr >> 12, h = (rr >> 10) & 3;
    const float* ptr = g_alpha + (size_t)rr*SS;
    float xv[32];
    float m = -1e30f;
    #pragma unroll
    for (int c = 0; c < 32; c++){
        int t = c*32 + lane;
        float mv = mask[b*SS + t];
        float x = ptr[t] + (mv - 1.0f)*1e11f;
        xv[c] = x;
        m = fmaxf(m, x);
    }
    #pragma unroll
    for (int off = 16; off; off >>= 1) m = fmaxf(m, __shfl_xor_sync(0xffffffffu, m, off));
    float sum = 0.f;
    #pragma unroll
    for (int c = 0; c < 32; c++){
        float e = __expf(xv[c] - m);
        xv[c] = e;
        sum += e;
    }
    #pragma unroll
    for (int off = 16; off; off >>= 1) sum += __shfl_xor_sync(0xffffffffu, sum, off);
    const float scale = wtw[h] / sum;
    __nv_bfloat16* oh = g_ahi + (size_t)rr*SS;
    __nv_bfloat16* ol = g_alo + (size_t)rr*SS;
    #pragma unroll
    for (int c = 0; c < 32; c++){
        float v = xv[c]*scale;
        __nv_bfloat16 hi = __float2bfloat16(v);
        oh[c*32 + lane] = hi;
        ol[c*32 + lane] = __float2bfloat16(v - __bfloat162float(hi));
    }
}

// ======================= K7 =======================
__global__ __launch_bounds__(256) void k_out(const float* __restrict__ mask,
                                             const float* __restrict__ wtb,
                                             const float* __restrict__ wrw,
                                             const float* __restrict__ wrb,
                                             float* __restrict__ out)
{
    const int rr = blockIdx.x*8 + (threadIdx.x >> 5);
    const int lane = threadIdx.x & 31;
    const float* att = g_att + (size_t)rr*H2;
    const float wb0 = wtb[0];
    float v[8];
    #pragma unroll
    for (int jj = 0; jj < 8; jj++)
        v[jj] = att[jj*32 + lane] + wb0;
    float l[3];
    #pragma unroll
    for (int o = 0; o < 3; o++){
        const float* wrow = wrw + o*H2;
        float p = 0.f;
        #pragma unroll
        for (int jj = 0; jj < 8; jj++)
            p = fmaf(v[jj], wrow[jj*32 + lane], p);
        #pragma unroll
        for (int off = 16; off; off >>= 1) p += __shfl_xor_sync(0xffffffffu, p, off);
        l[o] = p + wrb[o];
    }
    if (lane == 0){
        float mx  = fmaxf(l[0], fmaxf(l[1], l[2]));
        float lse = mx + logf(__expf(l[0]-mx) + __expf(l[1]-mx) + __expf(l[2]-mx));
        float mv  = mask[rr];
        out[rr*3+0] = (l[0] - lse)*mv;
        out[rr*3+1] = (l[1] - lse)*mv;
        out[rr*3+2] = (l[2] - lse)*mv;
    }
}

// ======================= launch =======================
extern "C" void kernel_launch(void* const* d_in, const int* in_sizes, int n_in,
                              void* d_out, int out_size)
{
    const int*   review = (const int*)  d_in[0];
    const float* mask   = (const float*)d_in[2];
    const float* emb    = (const float*)d_in[3];
    const float* wihf   = (const float*)d_in[4];
    const float* whhf   = (const float*)d_in[5];
    const float* bihf   = (const float*)d_in[6];
    const float* bhhf   = (const float*)d_in[7];
    const float* wihb   = (const float*)d_in[8];
    const float* whhb   = (const float*)d_in[9];
    const float* bihb   = (const float*)d_in[10];
    const float* bhhb   = (const float*)d_in[11];
    const float* wm     = (const float*)d_in[12];
    const float* wtw    = (const float*)d_in[13];
    const float* wtb    = (const float*)d_in[14];
    const float* wrw    = (const float*)d_in[15];
    const float* wrb    = (const float*)d_in[16];

    cudaFuncSetAttribute(k_mma<0,256>,  cudaFuncAttributeMaxDynamicSharedMemorySize, MMASM);
    cudaFuncSetAttribute(k_mma<1,256>,  cudaFuncAttributeMaxDynamicSharedMemorySize, MMASM);
    cudaFuncSetAttribute(k_mma<2,4096>, cudaFuncAttributeMaxDynamicSharedMemorySize, MMASM);
    cudaFuncSetAttribute(k_mma<3,320>,  cudaFuncAttributeMaxDynamicSharedMemorySize, MMASM);

    k_detect<<<1, 32>>>(review);
    k_embcvt<<<32000, 256>>>(emb);
    k_wihcvt<<<dim3(G3, 2), 256>>>(wihf, wihb);
    k_wmT<<<dim3(8, 8, 4), dim3(32, 8)>>>(wm);
    k_mma<3,320><<<dim3(3, 128, 2), 256, MMASM>>>(review, bihf, bihb);   // gx
    k_gru<<<dim3(16, 2), 512>>>(whhf, bhhf, whhb, bhhb);
    k_rhT<<<dim3(32, 8, 16), dim3(32, 8)>>>();
    k_mma<0,256><<<dim3(2, 128, 4),  256, MMASM>>>(nullptr, nullptr, nullptr);   // q
    k_mma<1,256><<<dim3(8, 8, 64),   256, MMASM>>>(nullptr, nullptr, nullptr);   // scores
    k_softmax<<<16384, 128>>>(mask, wtw);
    k_mma<2,4096><<<dim3(2, 8, 16),  256, MMASM>>>(nullptr, nullptr, nullptr);   // att
    k_out<<<2048, 256>>>(mask, wtb, wrw, wrb, (float*)d_out);
}